// round 3
// baseline (speedup 1.0000x reference)
#include <cuda_runtime.h>
#include <cuda_bf16.h>
#include <math.h>
#include <stdint.h>

// Problem constants
#define BT    8
#define LSEQ  8192
#define HID   512
#define PDIM  256
#define MROWS (BT * LSEQ)     // 65536 tokens
#define NCOLS 512             // 2*P (re | im)
#define KDIM  512             // H (GEMM1) and 2P (GEMM2)
#define NCH   64              // scan chunks
#define TCH   128             // steps per chunk (NCH*TCH == LSEQ)
#define NSEQ  (BT * 512)      // 4096 independent real 2-state scans

// GEMM tiling
#define BM 128
#define BN 128
#define BK 32
#define BKP 40                // padded k-stride (80B = 20 banks -> conflict-free frags)

// Scratch (static device memory: allocation-free per harness rules)
__device__ float g_W1[KDIM * NCOLS];            // [k=h][n]  n<256: B_re[n][h], else B_im
__device__ float g_W2[KDIM * NCOLS];            // [k=n][h]  n<256: C_re[h][n], else -C_im
__device__ float g_Bu[(size_t)MROWS * NCOLS];   // 128 MB
__device__ float g_ys[(size_t)MROWS * NCOLS];   // 128 MB
__device__ float g_cf[PDIM * 8];                // per p: s, s^2, c12, c21, c22
__device__ float g_mp[PDIM * 4];                // per p: M^TCH (2x2)
__device__ float g_loc1[NCH * NSEQ];
__device__ float g_loc2[NCH * NSEQ];
__device__ float g_car1[NCH * NSEQ];
__device__ float g_car2[NCH * NSEQ];

// ---------------------------------------------------------------------------
// helpers
// ---------------------------------------------------------------------------
__device__ __forceinline__ uint32_t pack_bf16(__nv_bfloat16 a, __nv_bfloat16 b) {
    return (uint32_t)__bfloat16_as_ushort(a) | ((uint32_t)__bfloat16_as_ushort(b) << 16);
}
__device__ __forceinline__ void split_f32(float v, __nv_bfloat16& hi, __nv_bfloat16& lo) {
    hi = __float2bfloat16(v);
    lo = __float2bfloat16(v - __bfloat162float(hi));
}
__device__ __forceinline__ void mma_bf16(float& c0, float& c1, float& c2, float& c3,
                                         uint32_t a0, uint32_t a1, uint32_t a2, uint32_t a3,
                                         uint32_t b0, uint32_t b1) {
    asm volatile(
        "mma.sync.aligned.m16n8k16.row.col.f32.bf16.bf16.f32 "
        "{%0,%1,%2,%3}, {%4,%5,%6,%7}, {%8,%9}, {%0,%1,%2,%3};\n"
        : "+f"(c0), "+f"(c1), "+f"(c2), "+f"(c3)
        : "r"(a0), "r"(a1), "r"(a2), "r"(a3), "r"(b0), "r"(b1));
}

// ---------------------------------------------------------------------------
// Kernel 0: per-p coefficients + M^TCH via repeated squaring
// ---------------------------------------------------------------------------
__global__ void prep_kernel(const float* __restrict__ steps_param,
                            const float* __restrict__ A_param) {
    int p = threadIdx.x;
    float s = 1.0f / (1.0f + expf(-steps_param[p]));
    float a = fmaxf(A_param[p], 0.0f);
    float c12 = -s * a;
    float c21 = s;
    float c22 = 1.0f - s * s * a;
    g_cf[p * 8 + 0] = s;
    g_cf[p * 8 + 1] = s * s;
    g_cf[p * 8 + 2] = c12;
    g_cf[p * 8 + 3] = c21;
    g_cf[p * 8 + 4] = c22;

    float ma = 1.0f, mb = c12, mc = c21, md = c22;
    #pragma unroll
    for (int i = 0; i < 7; i++) {
        float na = ma * ma + mb * mc;
        float nb = ma * mb + mb * md;
        float nc = mc * ma + md * mc;
        float nd = mc * mb + md * md;
        ma = na; mb = nb; mc = nc; md = nd;
    }
    g_mp[p * 4 + 0] = ma;
    g_mp[p * 4 + 1] = mb;
    g_mp[p * 4 + 2] = mc;
    g_mp[p * 4 + 3] = md;
}

// ---------------------------------------------------------------------------
// Kernel 1: build packed GEMM weights from B (P,H,2) and C (H,P,2)
// ---------------------------------------------------------------------------
__global__ void buildW_kernel(const float* __restrict__ Bp,
                              const float* __restrict__ Cp) {
    int idx = blockIdx.x * 256 + threadIdx.x;   // 0 .. 512*512-1
    {
        int h = idx >> 9;
        int n = idx & 511;
        float v = (n < 256) ? Bp[n * (HID * 2) + h * 2 + 0]
                            : Bp[(n - 256) * (HID * 2) + h * 2 + 1];
        g_W1[idx] = v;
    }
    {
        int n = idx >> 9;
        int h = idx & 511;
        float v = (n < 256) ? Cp[h * (PDIM * 2) + n * 2 + 0]
                            : -Cp[h * (PDIM * 2) + (n - 256) * 2 + 1];
        g_W2[idx] = v;
    }
}

// ---------------------------------------------------------------------------
// Tensor-core GEMM via split-bf16 mma.sync (3-term hi/lo).
// C[M,N] = A[M,K] @ W[K,N]   (fp32 in/out, fp32 accumulate)
// Block 128x128x32, 256 threads = 8 warps (4 m x 2 n), warp tile 32x64.
// MODE 0: g_Bu = x @ g_W1       MODE 1: y = g_ys @ g_W2 + D .* x
// ---------------------------------------------------------------------------
template <int MODE>
__global__ void __launch_bounds__(256)
mma_gemm(const float* __restrict__ Aext, float* __restrict__ Cext,
         const float* __restrict__ xres, const float* __restrict__ Dv) {
    __shared__ __align__(16) __nv_bfloat16 As_hi[BM][BKP];   // [m][k]
    __shared__ __align__(16) __nv_bfloat16 As_lo[BM][BKP];
    __shared__ __align__(16) __nv_bfloat16 Bs_hi[BN][BKP];   // [n][k] (transposed)
    __shared__ __align__(16) __nv_bfloat16 Bs_lo[BN][BKP];

    const float* Amat = (MODE == 0) ? Aext : g_ys;
    const float* W    = (MODE == 0) ? g_W1 : g_W2;
    float*       Cout = (MODE == 0) ? g_Bu : Cext;

    const int tid  = threadIdx.x;
    const int lane = tid & 31;
    const int wid  = tid >> 5;
    const int grp  = lane >> 2;   // 0..7
    const int tig  = lane & 3;    // 0..3
    const int warp_m = wid & 3;   // 0..3 -> 32 rows each
    const int warp_n = wid >> 2;  // 0..1 -> 64 cols each

    const int mBase = blockIdx.y << 7;
    const int nBase = blockIdx.x << 7;

    float c[2][8][4];
    #pragma unroll
    for (int mt = 0; mt < 2; mt++)
        #pragma unroll
        for (int nt = 0; nt < 8; nt++)
            #pragma unroll
            for (int r = 0; r < 4; r++) c[mt][nt][r] = 0.0f;

    const float* Aptr = Amat + (size_t)mBase * KDIM;
    const float* Wptr = W + nBase;

    for (int k0 = 0; k0 < KDIM; k0 += BK) {
        // ---- load & split A tile: 128 x 32 fp32 -> hi/lo bf16 [m][k] ----
        #pragma unroll
        for (int it = 0; it < 4; it++) {
            int lin = tid + (it << 8);          // 0..1023 (float4 index)
            int r   = lin >> 3;                 // m row 0..127
            int kq  = (lin & 7) << 2;           // k 0,4,...,28
            float4 v = *(const float4*)(Aptr + (size_t)r * KDIM + k0 + kq);
            __nv_bfloat16 h0,l0,h1,l1,h2,l2,h3,l3;
            split_f32(v.x, h0, l0); split_f32(v.y, h1, l1);
            split_f32(v.z, h2, l2); split_f32(v.w, h3, l3);
            uint2 ph = make_uint2(pack_bf16(h0, h1), pack_bf16(h2, h3));
            uint2 pl = make_uint2(pack_bf16(l0, l1), pack_bf16(l2, l3));
            *(uint2*)&As_hi[r][kq] = ph;
            *(uint2*)&As_lo[r][kq] = pl;
        }
        // ---- load & split W tile: 32 x 128 fp32, store transposed [n][k] ----
        #pragma unroll
        for (int it = 0; it < 4; it++) {
            int lin = tid + (it << 8);          // 0..1023
            int kr  = lin >> 5;                 // k row 0..31
            int nq  = (lin & 31) << 2;          // n 0,4,...,124
            float4 w = *(const float4*)(Wptr + (size_t)(k0 + kr) * NCOLS + nq);
            __nv_bfloat16 h, l;
            split_f32(w.x, h, l); Bs_hi[nq + 0][kr] = h; Bs_lo[nq + 0][kr] = l;
            split_f32(w.y, h, l); Bs_hi[nq + 1][kr] = h; Bs_lo[nq + 1][kr] = l;
            split_f32(w.z, h, l); Bs_hi[nq + 2][kr] = h; Bs_lo[nq + 2][kr] = l;
            split_f32(w.w, h, l); Bs_hi[nq + 3][kr] = h; Bs_lo[nq + 3][kr] = l;
        }
        __syncthreads();

        // ---- compute: 2 k16 slices ----
        #pragma unroll
        for (int ks = 0; ks < 2; ks++) {
            const int kc = (ks << 4) + (tig << 1);  // k col for this thread's pairs
            // A fragments (2 m-tiles), documented m16n8k16 layout
            uint32_t ah[2][4], al[2][4];
            #pragma unroll
            for (int mt = 0; mt < 2; mt++) {
                int r0 = (warp_m << 5) + (mt << 4) + grp;
                ah[mt][0] = *(const uint32_t*)&As_hi[r0    ][kc    ];
                ah[mt][1] = *(const uint32_t*)&As_hi[r0 + 8][kc    ];
                ah[mt][2] = *(const uint32_t*)&As_hi[r0    ][kc + 8];
                ah[mt][3] = *(const uint32_t*)&As_hi[r0 + 8][kc + 8];
                al[mt][0] = *(const uint32_t*)&As_lo[r0    ][kc    ];
                al[mt][1] = *(const uint32_t*)&As_lo[r0 + 8][kc    ];
                al[mt][2] = *(const uint32_t*)&As_lo[r0    ][kc + 8];
                al[mt][3] = *(const uint32_t*)&As_lo[r0 + 8][kc + 8];
            }
            #pragma unroll
            for (int nt = 0; nt < 8; nt++) {
                int nrow = (warp_n << 6) + (nt << 3) + grp;
                uint32_t bh0 = *(const uint32_t*)&Bs_hi[nrow][kc];
                uint32_t bh1 = *(const uint32_t*)&Bs_hi[nrow][kc + 8];
                uint32_t bl0 = *(const uint32_t*)&Bs_lo[nrow][kc];
                uint32_t bl1 = *(const uint32_t*)&Bs_lo[nrow][kc + 8];
                #pragma unroll
                for (int mt = 0; mt < 2; mt++) {
                    float* cc = c[mt][nt];
                    mma_bf16(cc[0], cc[1], cc[2], cc[3],
                             ah[mt][0], ah[mt][1], ah[mt][2], ah[mt][3], bh0, bh1);
                    mma_bf16(cc[0], cc[1], cc[2], cc[3],
                             ah[mt][0], ah[mt][1], ah[mt][2], ah[mt][3], bl0, bl1);
                    mma_bf16(cc[0], cc[1], cc[2], cc[3],
                             al[mt][0], al[mt][1], al[mt][2], al[mt][3], bh0, bh1);
                }
            }
        }
        __syncthreads();
    }

    // ---- epilogue ----
    #pragma unroll
    for (int nt = 0; nt < 8; nt++) {
        int col = nBase + (warp_n << 6) + (nt << 3) + (tig << 1);
        float2 d;
        if (MODE == 1) d = *(const float2*)(Dv + col);
        #pragma unroll
        for (int mt = 0; mt < 2; mt++) {
            int row0 = mBase + (warp_m << 5) + (mt << 4) + grp;
            size_t o0 = (size_t)row0 * NCOLS + col;
            size_t o1 = o0 + ((size_t)8 * NCOLS);
            float2 v0 = make_float2(c[mt][nt][0], c[mt][nt][1]);
            float2 v1 = make_float2(c[mt][nt][2], c[mt][nt][3]);
            if (MODE == 1) {
                float2 x0 = *(const float2*)(xres + o0);
                float2 x1 = *(const float2*)(xres + o1);
                v0.x += d.x * x0.x; v0.y += d.y * x0.y;
                v1.x += d.x * x1.x; v1.y += d.y * x1.y;
            }
            *(float2*)(Cout + o0) = v0;
            *(float2*)(Cout + o1) = v1;
        }
    }
}

// ---------------------------------------------------------------------------
// Scan pass 1: chunk-local scans with zero init; store final (z1,z2)
// ---------------------------------------------------------------------------
__global__ void __launch_bounds__(256) scan_pass1() {
    int c = blockIdx.x, b = blockIdx.y, z = blockIdx.z;
    int p = threadIdx.x;
    int n = (z << 8) + p;
    int sid = (b << 9) + n;

    float s1  = g_cf[p * 8 + 0];
    float s2  = g_cf[p * 8 + 1];
    float c12 = g_cf[p * 8 + 2];
    float c21 = g_cf[p * 8 + 3];
    float c22 = g_cf[p * 8 + 4];

    size_t base = ((size_t)(b * LSEQ + c * TCH) << 9) + n;
    float z1 = 0.0f, z2 = 0.0f;
    #pragma unroll 8
    for (int i = 0; i < TCH; i++) {
        float bu = g_Bu[base + ((size_t)i << 9)];
        float nz1 = fmaf(c12, z2, fmaf(s1, bu, z1));
        float nz2 = fmaf(c21, z1, fmaf(c22, z2, s2 * bu));
        z1 = nz1; z2 = nz2;
    }
    g_loc1[c * NSEQ + sid] = z1;
    g_loc2[c * NSEQ + sid] = z2;
}

// ---------------------------------------------------------------------------
// Scan pass 2: sequential carry scan across chunks (exclusive carries)
// ---------------------------------------------------------------------------
__global__ void __launch_bounds__(256) scan_pass2() {
    int sid = blockIdx.x * 256 + threadIdx.x;   // 0..4095
    int p = sid & 255;
    float m11 = g_mp[p * 4 + 0];
    float m12 = g_mp[p * 4 + 1];
    float m21 = g_mp[p * 4 + 2];
    float m22 = g_mp[p * 4 + 3];

    float c1 = 0.0f, c2 = 0.0f;
    for (int c = 0; c < NCH; c++) {
        g_car1[c * NSEQ + sid] = c1;
        g_car2[c * NSEQ + sid] = c2;
        float l1 = g_loc1[c * NSEQ + sid];
        float l2 = g_loc2[c * NSEQ + sid];
        float n1 = fmaf(m11, c1, fmaf(m12, c2, l1));
        float n2 = fmaf(m21, c1, fmaf(m22, c2, l2));
        c1 = n1; c2 = n2;
    }
}

// ---------------------------------------------------------------------------
// Scan pass 3: replay chunks with correct carry-in, write ys = z2
// ---------------------------------------------------------------------------
__global__ void __launch_bounds__(256) scan_pass3() {
    int c = blockIdx.x, b = blockIdx.y, z = blockIdx.z;
    int p = threadIdx.x;
    int n = (z << 8) + p;
    int sid = (b << 9) + n;

    float s1  = g_cf[p * 8 + 0];
    float s2  = g_cf[p * 8 + 1];
    float c12 = g_cf[p * 8 + 2];
    float c21 = g_cf[p * 8 + 3];
    float c22 = g_cf[p * 8 + 4];

    size_t base = ((size_t)(b * LSEQ + c * TCH) << 9) + n;
    float z1 = g_car1[c * NSEQ + sid];
    float z2 = g_car2[c * NSEQ + sid];
    #pragma unroll 8
    for (int i = 0; i < TCH; i++) {
        float bu = g_Bu[base + ((size_t)i << 9)];
        float nz1 = fmaf(c12, z2, fmaf(s1, bu, z1));
        float nz2 = fmaf(c21, z1, fmaf(c22, z2, s2 * bu));
        z1 = nz1; z2 = nz2;
        g_ys[base + ((size_t)i << 9)] = z2;
    }
}

// ---------------------------------------------------------------------------
// Launch
// ---------------------------------------------------------------------------
extern "C" void kernel_launch(void* const* d_in, const int* in_sizes, int n_in,
                              void* d_out, int out_size) {
    const float* x  = (const float*)d_in[0];   // (8, 8192, 512)
    const float* sp = (const float*)d_in[1];   // (256,)
    const float* Ap = (const float*)d_in[2];   // (256,)
    const float* Bp = (const float*)d_in[3];   // (256, 512, 2)
    const float* Cp = (const float*)d_in[4];   // (512, 256, 2)
    const float* Dp = (const float*)d_in[5];   // (512,)
    float* y = (float*)d_out;                  // (8, 8192, 512)

    prep_kernel<<<1, 256>>>(sp, Ap);
    buildW_kernel<<<1024, 256>>>(Bp, Cp);

    // GEMM1: Bu = x @ W1   (tensor cores, split-bf16)
    mma_gemm<0><<<dim3(NCOLS / BN, MROWS / BM), 256>>>(x, nullptr, nullptr, nullptr);

    // Chunked linear scan
    scan_pass1<<<dim3(NCH, BT, 2), 256>>>();
    scan_pass2<<<16, 256>>>();
    scan_pass3<<<dim3(NCH, BT, 2), 256>>>();

    // GEMM2 + epilogue: y = ys @ W2 + D .* x  (tensor cores, split-bf16)
    mma_gemm<1><<<dim3(NCOLS / BN, MROWS / BM), 256>>>(nullptr, y, x, Dp);
}

// round 7
// speedup vs baseline: 2.4632x; 2.4632x over previous
#include <cuda_runtime.h>
#include <cuda_bf16.h>
#include <math.h>
#include <stdint.h>

// R6: tcgen05 is unavailable (harness ptxas targets sm_100, not sm_100a —
// proven by R6 compile errors). Pivot to the R3-proven mma.sync bf16 path,
// now optimized: pre-split bf16 hi/lo inputs in gmem, cp.async double-buffered
// K pipeline, ldmatrix.x4 fragment loads, 128x128x64 block tile.

// Problem constants
#define BT    8
#define LSEQ  8192
#define HID   512
#define PDIM  256
#define MROWS (BT * LSEQ)     // 65536 tokens
#define NCOLS 512             // 2*P (re | im)
#define KDIM  512
#define NCH   64              // scan chunks
#define TCH   128             // steps per chunk
#define NSEQ  (BT * 512)      // 4096 independent real 2-state scans

// GEMM tiling
#define BM 128
#define BN 128
#define BK 64                 // 128 B of bf16 per row -> SW128 swizzle
#define NS (KDIM / BK)        // 8 stages

// SMEM stage layout (per stage 64 KB): Ah 16K | Al 16K | Bh 16K | Bl 16K
#define STG_BYTES 65536
#define OFF_AH 0
#define OFF_AL 16384
#define OFF_BH 32768
#define OFF_BL 49152
#define SM_TOTAL (2 * STG_BYTES)

#define SWZ(b) ((b) ^ (((b) >> 3) & 0x70))

// ---------------------------------------------------------------------------
// Static device scratch
// ---------------------------------------------------------------------------
__device__ __nv_bfloat16 g_W1h[KDIM * NCOLS];   // [n][k]
__device__ __nv_bfloat16 g_W1l[KDIM * NCOLS];
__device__ __nv_bfloat16 g_W2h[KDIM * NCOLS];
__device__ __nv_bfloat16 g_W2l[KDIM * NCOLS];
__device__ __nv_bfloat16 g_xh[(size_t)MROWS * NCOLS];   // x split hi
__device__ __nv_bfloat16 g_xl[(size_t)MROWS * NCOLS];   // x split lo
__device__ float g_Bu[(size_t)MROWS * NCOLS];           // 128 MB
__device__ __nv_bfloat16 g_ysh[(size_t)MROWS * NCOLS];  // 64 MB
__device__ __nv_bfloat16 g_ysl[(size_t)MROWS * NCOLS];  // 64 MB
__device__ float g_cf[PDIM * 8];
__device__ float g_mp[PDIM * 4];
__device__ float g_loc1[NCH * NSEQ];
__device__ float g_loc2[NCH * NSEQ];
__device__ float g_car1[NCH * NSEQ];
__device__ float g_car2[NCH * NSEQ];

// ---------------------------------------------------------------------------
// helpers
// ---------------------------------------------------------------------------
__device__ __forceinline__ uint32_t smem_u32(const void* p) {
    uint32_t a;
    asm("{ .reg .u64 t; cvta.to.shared.u64 t, %1; cvt.u32.u64 %0, t; }" : "=r"(a) : "l"(p));
    return a;
}
__device__ __forceinline__ void cp_async16(uint32_t dst, const void* src) {
    asm volatile("cp.async.cg.shared.global [%0], [%1], 16;" :: "r"(dst), "l"(src) : "memory");
}
__device__ __forceinline__ void cp_commit() {
    asm volatile("cp.async.commit_group;" ::: "memory");
}
template <int N>
__device__ __forceinline__ void cp_wait() {
    asm volatile("cp.async.wait_group %0;" :: "n"(N) : "memory");
}
__device__ __forceinline__ void ldsm_x4(uint32_t* r, uint32_t addr) {
    asm volatile("ldmatrix.sync.aligned.m8n8.x4.shared.b16 {%0,%1,%2,%3}, [%4];"
                 : "=r"(r[0]), "=r"(r[1]), "=r"(r[2]), "=r"(r[3]) : "r"(addr));
}
__device__ __forceinline__ void mma_bf16(float* c, uint32_t a0, uint32_t a1, uint32_t a2,
                                         uint32_t a3, uint32_t b0, uint32_t b1) {
    asm volatile(
        "mma.sync.aligned.m16n8k16.row.col.f32.bf16.bf16.f32 "
        "{%0,%1,%2,%3}, {%4,%5,%6,%7}, {%8,%9}, {%0,%1,%2,%3};\n"
        : "+f"(c[0]), "+f"(c[1]), "+f"(c[2]), "+f"(c[3])
        : "r"(a0), "r"(a1), "r"(a2), "r"(a3), "r"(b0), "r"(b1));
}
__device__ __forceinline__ void split_f32(float v, __nv_bfloat16& hi, __nv_bfloat16& lo) {
    hi = __float2bfloat16(v);
    lo = __float2bfloat16(v - __bfloat162float(hi));
}
__device__ __forceinline__ uint32_t pack_bf16(__nv_bfloat16 a, __nv_bfloat16 b) {
    return (uint32_t)__bfloat16_as_ushort(a) | ((uint32_t)__bfloat16_as_ushort(b) << 16);
}

// ---------------------------------------------------------------------------
// Kernel 0: per-p coefficients + M^TCH
// ---------------------------------------------------------------------------
__global__ void prep_kernel(const float* __restrict__ steps_param,
                            const float* __restrict__ A_param) {
    int p = threadIdx.x;
    float s = 1.0f / (1.0f + expf(-steps_param[p]));
    float a = fmaxf(A_param[p], 0.0f);
    float c12 = -s * a;
    float c21 = s;
    float c22 = 1.0f - s * s * a;
    g_cf[p * 8 + 0] = s;
    g_cf[p * 8 + 1] = s * s;
    g_cf[p * 8 + 2] = c12;
    g_cf[p * 8 + 3] = c21;
    g_cf[p * 8 + 4] = c22;

    float ma = 1.0f, mb = c12, mc = c21, md = c22;
    #pragma unroll
    for (int i = 0; i < 7; i++) {
        float na = ma * ma + mb * mc;
        float nb = ma * mb + mb * md;
        float nc = mc * ma + md * mc;
        float nd = mc * mb + md * md;
        ma = na; mb = nb; mc = nc; md = nd;
    }
    g_mp[p * 4 + 0] = ma;
    g_mp[p * 4 + 1] = mb;
    g_mp[p * 4 + 2] = mc;
    g_mp[p * 4 + 3] = md;
}

// ---------------------------------------------------------------------------
// Kernel 1: pack weights into [n][k] bf16 hi/lo
// ---------------------------------------------------------------------------
__global__ void buildW_kernel(const float* __restrict__ Bp,
                              const float* __restrict__ Cp) {
    int idx = blockIdx.x * 256 + threadIdx.x;   // 0 .. 512*512-1
    // W1[n][k]: k = h;  n<256: B_re[n][h], else B_im[n-256][h]
    {
        int k = idx >> 9;
        int n = idx & 511;
        float v = (n < 256) ? Bp[n * (HID * 2) + k * 2 + 0]
                            : Bp[(n - 256) * (HID * 2) + k * 2 + 1];
        __nv_bfloat16 hi, lo; split_f32(v, hi, lo);
        g_W1h[n * KDIM + k] = hi;
        g_W1l[n * KDIM + k] = lo;
    }
    // W2[n][k]: n = h, k = p-ext;  k<256: C_re[h][k], else -C_im[h][k-256]
    {
        int k = idx >> 9;
        int n = idx & 511;
        float v = (k < 256) ? Cp[n * (PDIM * 2) + k * 2 + 0]
                            : -Cp[n * (PDIM * 2) + (k - 256) * 2 + 1];
        __nv_bfloat16 hi, lo; split_f32(v, hi, lo);
        g_W2h[n * KDIM + k] = hi;
        g_W2l[n * KDIM + k] = lo;
    }
}

// ---------------------------------------------------------------------------
// Kernel 2: split x into bf16 hi/lo (enables cp.async in GEMM1)
// grid 32768 x 256; each thread handles one float4
// ---------------------------------------------------------------------------
__global__ void __launch_bounds__(256) splitX_kernel(const float* __restrict__ x) {
    size_t i = ((size_t)blockIdx.x * 256 + threadIdx.x) << 2;
    float4 v = *(const float4*)(x + i);
    __nv_bfloat16 h0,l0,h1,l1,h2,l2,h3,l3;
    split_f32(v.x, h0, l0); split_f32(v.y, h1, l1);
    split_f32(v.z, h2, l2); split_f32(v.w, h3, l3);
    *(uint2*)(g_xh + i) = make_uint2(pack_bf16(h0, h1), pack_bf16(h2, h3));
    *(uint2*)(g_xl + i) = make_uint2(pack_bf16(l0, l1), pack_bf16(l2, l3));
}

// ---------------------------------------------------------------------------
// mma.sync GEMM, cp.async double-buffered, ldmatrix fragments.
// C[M,N] = A[M,K] @ W[K,N], A/W as bf16 hi/lo (3-term split product).
// Block 128x128, K stages of 64. 256 thr = 8 warps (2 m x 4 n), warp 64x32.
// MODE 0: A = x(split) -> g_Bu        MODE 1: A = ys(split) -> y + D.*x
// ---------------------------------------------------------------------------
template <int MODE>
__global__ void __launch_bounds__(256, 1)
mma_gemm(float* __restrict__ Cext, const float* __restrict__ xres,
         const float* __restrict__ Dv) {
    extern __shared__ __align__(128) char smem[];
    const uint32_t sb = smem_u32(smem);

    const __nv_bfloat16* Ah = (MODE == 0) ? g_xh : g_ysh;
    const __nv_bfloat16* Al = (MODE == 0) ? g_xl : g_ysl;
    const __nv_bfloat16* Wh = (MODE == 0) ? g_W1h : g_W2h;
    const __nv_bfloat16* Wl = (MODE == 0) ? g_W1l : g_W2l;
    float* Cout = (MODE == 0) ? g_Bu : Cext;

    const int tid  = threadIdx.x;
    const int lane = tid & 31;
    const int wid  = tid >> 5;
    const int warp_m = wid & 1;        // 0..1 -> 64 rows
    const int warp_n = wid >> 1;       // 0..3 -> 32 cols
    const int mBase = blockIdx.y << 7;
    const int nBase = blockIdx.x << 7;

    // ldmatrix per-lane row/col mapping
    const int rl   = (lane & 7) + ((lane >> 3) & 1) * 8;  // row within 16-row tile
    const int kq16 = (lane >> 4) << 4;                    // +16B for k8-15 matrices

    // per-thread precomputed row offsets (byte) and swizzle XOR values
    uint32_t aRow[4], aXor[4];
    #pragma unroll
    for (int mt = 0; mt < 4; mt++) {
        int row = warp_m * 64 + mt * 16 + rl;
        aRow[mt] = row << 7;
        aXor[mt] = (row & 7) << 4;
    }
    uint32_t bRow[2], bXor[2];
    #pragma unroll
    for (int g = 0; g < 2; g++) {
        int row = warp_n * 32 + g * 16 + rl;
        bRow[g] = row << 7;
        bXor[g] = (row & 7) << 4;
    }

    float c[4][4][4];
    #pragma unroll
    for (int mt = 0; mt < 4; mt++)
        #pragma unroll
        for (int nt = 0; nt < 4; nt++)
            #pragma unroll
            for (int r = 0; r < 4; r++) c[mt][nt][r] = 0.0f;

    // ---- stage loader: 128 rows x 64 k (=8 x 16B segs per row) per matrix ----
    auto load_stage = [&](int kc, int buf) {
        const uint32_t s0 = sb + buf * STG_BYTES;
        const int k0 = kc * BK;
        #pragma unroll
        for (int it = 0; it < 4; it++) {
            int lin = tid + (it << 8);      // 0..1023
            int r = lin >> 3;               // row 0..127
            int s = lin & 7;                // 16B seg
            uint32_t d = SWZ((r << 7) + (s << 4));
            size_t srcA = (size_t)(mBase + r) * KDIM + k0 + (s << 3);
            size_t srcB = (size_t)(nBase + r) * KDIM + k0 + (s << 3);
            cp_async16(s0 + OFF_AH + d, Ah + srcA);
            cp_async16(s0 + OFF_AL + d, Al + srcA);
            cp_async16(s0 + OFF_BH + d, Wh + srcB);
            cp_async16(s0 + OFF_BL + d, Wl + srcB);
        }
        cp_commit();
    };

    load_stage(0, 0);

    for (int kc = 0; kc < NS; kc++) {
        if (kc + 1 < NS) load_stage(kc + 1, (kc + 1) & 1);
        if (kc + 1 < NS) cp_wait<1>(); else cp_wait<0>();
        __syncthreads();

        const uint32_t s0 = sb + (kc & 1) * STG_BYTES;
        const uint32_t aHi = s0 + OFF_AH, aLo = s0 + OFF_AL;
        const uint32_t bHi = s0 + OFF_BH, bLo = s0 + OFF_BL;

        #pragma unroll
        for (int ks = 0; ks < 4; ks++) {
            const uint32_t kb = (ks << 5) + kq16;   // byte offset in 128B row
            uint32_t ah[4][4], al[4][4];
            #pragma unroll
            for (int mt = 0; mt < 4; mt++) {
                ldsm_x4(ah[mt], aHi + aRow[mt] + (kb ^ aXor[mt]));
                ldsm_x4(al[mt], aLo + aRow[mt] + (kb ^ aXor[mt]));
            }
            #pragma unroll
            for (int g = 0; g < 2; g++) {
                uint32_t bh[4], bl[4];
                ldsm_x4(bh, bHi + bRow[g] + (kb ^ bXor[g]));
                ldsm_x4(bl, bLo + bRow[g] + (kb ^ bXor[g]));
                #pragma unroll
                for (int n2 = 0; n2 < 2; n2++) {
                    const int nt = g * 2 + n2;
                    const uint32_t b0h = bh[n2], b1h = bh[n2 + 2];
                    const uint32_t b0l = bl[n2], b1l = bl[n2 + 2];
                    #pragma unroll
                    for (int mt = 0; mt < 4; mt++) {
                        float* cc = c[mt][nt];
                        mma_bf16(cc, ah[mt][0], ah[mt][1], ah[mt][2], ah[mt][3], b0h, b1h);
                        mma_bf16(cc, ah[mt][0], ah[mt][1], ah[mt][2], ah[mt][3], b0l, b1l);
                        mma_bf16(cc, al[mt][0], al[mt][1], al[mt][2], al[mt][3], b0h, b1h);
                    }
                }
            }
        }
        __syncthreads();
    }

    // ---- epilogue ----
    const int grp = lane >> 2;
    const int tig = lane & 3;
    #pragma unroll
    for (int nt = 0; nt < 4; nt++) {
        int col = nBase + warp_n * 32 + nt * 8 + (tig << 1);
        float2 d;
        if (MODE == 1) d = *(const float2*)(Dv + col);
        #pragma unroll
        for (int mt = 0; mt < 4; mt++) {
            int row0 = mBase + warp_m * 64 + mt * 16 + grp;
            size_t o0 = (size_t)row0 * NCOLS + col;
            size_t o1 = o0 + ((size_t)8 * NCOLS);
            float2 v0 = make_float2(c[mt][nt][0], c[mt][nt][1]);
            float2 v1 = make_float2(c[mt][nt][2], c[mt][nt][3]);
            if (MODE == 1) {
                float2 x0 = *(const float2*)(xres + o0);
                float2 x1 = *(const float2*)(xres + o1);
                v0.x += d.x * x0.x; v0.y += d.y * x0.y;
                v1.x += d.x * x1.x; v1.y += d.y * x1.y;
            }
            *(float2*)(Cout + o0) = v0;
            *(float2*)(Cout + o1) = v1;
        }
    }
}

// ---------------------------------------------------------------------------
// Scan pass 1: chunk-local scans with zero init; store final (z1,z2)
// ---------------------------------------------------------------------------
__global__ void __launch_bounds__(256) scan_pass1() {
    int c = blockIdx.x, b = blockIdx.y, z = blockIdx.z;
    int p = threadIdx.x;
    int n = (z << 8) + p;
    int sid = (b << 9) + n;

    float s1  = g_cf[p * 8 + 0];
    float s2  = g_cf[p * 8 + 1];
    float c12 = g_cf[p * 8 + 2];
    float c21 = g_cf[p * 8 + 3];
    float c22 = g_cf[p * 8 + 4];

    size_t base = ((size_t)(b * LSEQ + c * TCH) << 9) + n;
    float z1 = 0.0f, z2 = 0.0f;
    #pragma unroll 8
    for (int i = 0; i < TCH; i++) {
        float bu = g_Bu[base + ((size_t)i << 9)];
        float nz1 = fmaf(c12, z2, fmaf(s1, bu, z1));
        float nz2 = fmaf(c21, z1, fmaf(c22, z2, s2 * bu));
        z1 = nz1; z2 = nz2;
    }
    g_loc1[c * NSEQ + sid] = z1;
    g_loc2[c * NSEQ + sid] = z2;
}

// ---------------------------------------------------------------------------
// Scan pass 2: sequential carry scan across chunks (exclusive carries)
// ---------------------------------------------------------------------------
__global__ void __launch_bounds__(256) scan_pass2() {
    int sid = blockIdx.x * 256 + threadIdx.x;   // 0..4095
    int p = sid & 255;
    float m11 = g_mp[p * 4 + 0];
    float m12 = g_mp[p * 4 + 1];
    float m21 = g_mp[p * 4 + 2];
    float m22 = g_mp[p * 4 + 3];

    float c1 = 0.0f, c2 = 0.0f;
    for (int c = 0; c < NCH; c++) {
        g_car1[c * NSEQ + sid] = c1;
        g_car2[c * NSEQ + sid] = c2;
        float l1 = g_loc1[c * NSEQ + sid];
        float l2 = g_loc2[c * NSEQ + sid];
        float n1 = fmaf(m11, c1, fmaf(m12, c2, l1));
        float n2 = fmaf(m21, c1, fmaf(m22, c2, l2));
        c1 = n1; c2 = n2;
    }
}

// ---------------------------------------------------------------------------
// Scan pass 3: replay with carry-in, emit ys split to bf16 hi/lo
// ---------------------------------------------------------------------------
__global__ void __launch_bounds__(256) scan_pass3() {
    int c = blockIdx.x, b = blockIdx.y, z = blockIdx.z;
    int p = threadIdx.x;
    int n = (z << 8) + p;
    int sid = (b << 9) + n;

    float s1  = g_cf[p * 8 + 0];
    float s2  = g_cf[p * 8 + 1];
    float c12 = g_cf[p * 8 + 2];
    float c21 = g_cf[p * 8 + 3];
    float c22 = g_cf[p * 8 + 4];

    size_t base = ((size_t)(b * LSEQ + c * TCH) << 9) + n;
    float z1 = g_car1[c * NSEQ + sid];
    float z2 = g_car2[c * NSEQ + sid];
    #pragma unroll 8
    for (int i = 0; i < TCH; i++) {
        float bu = g_Bu[base + ((size_t)i << 9)];
        float nz1 = fmaf(c12, z2, fmaf(s1, bu, z1));
        float nz2 = fmaf(c21, z1, fmaf(c22, z2, s2 * bu));
        z1 = nz1; z2 = nz2;
        __nv_bfloat16 hi, lo; split_f32(z2, hi, lo);
        g_ysh[base + ((size_t)i << 9)] = hi;
        g_ysl[base + ((size_t)i << 9)] = lo;
    }
}

// ---------------------------------------------------------------------------
// Launch
// ---------------------------------------------------------------------------
extern "C" void kernel_launch(void* const* d_in, const int* in_sizes, int n_in,
                              void* d_out, int out_size) {
    const float* x  = (const float*)d_in[0];   // (8, 8192, 512)
    const float* sp = (const float*)d_in[1];   // (256,)
    const float* Ap = (const float*)d_in[2];   // (256,)
    const float* Bp = (const float*)d_in[3];   // (256, 512, 2)
    const float* Cp = (const float*)d_in[4];   // (512, 256, 2)
    const float* Dp = (const float*)d_in[5];   // (512,)
    float* y = (float*)d_out;                  // (8, 8192, 512)

    cudaFuncSetAttribute(mma_gemm<0>, cudaFuncAttributeMaxDynamicSharedMemorySize, SM_TOTAL);
    cudaFuncSetAttribute(mma_gemm<1>, cudaFuncAttributeMaxDynamicSharedMemorySize, SM_TOTAL);

    prep_kernel<<<1, 256>>>(sp, Ap);
    buildW_kernel<<<1024, 256>>>(Bp, Cp);
    splitX_kernel<<<(MROWS * NCOLS) / 1024, 256>>>(x);

    // GEMM1: Bu = x @ W1
    mma_gemm<0><<<dim3(NCOLS / BN, MROWS / BM), 256, SM_TOTAL>>>(nullptr, nullptr, nullptr);

    // Chunked linear scan (pass3 emits ys as bf16 hi/lo)
    scan_pass1<<<dim3(NCH, BT, 2), 256>>>();
    scan_pass2<<<16, 256>>>();
    scan_pass3<<<dim3(NCH, BT, 2), 256>>>();

    // GEMM2 + epilogue: y = ys @ W2 + D .* x
    mma_gemm<1><<<dim3(NCOLS / BN, MROWS / BM), 256, SM_TOTAL>>>(y, x, Dp);
}

// round 8
// speedup vs baseline: 2.4756x; 1.0050x over previous
#include <cuda_runtime.h>
#include <cuda_bf16.h>
#include <math.h>
#include <stdint.h>

// R7: raise mma.sync issue efficiency. ncu R7: tensor=58.5%, occ=12.5% (1 CTA/SM,
// 2 syncs/stage). Now: 3-stage cp.async ring (BK=32, 1 sync/stage), SW64 swizzle,
// __launch_bounds__(256,2) for 2 CTAs/SM (96KB smem/CTA, <=128 regs).

// Problem constants
#define BT    8
#define LSEQ  8192
#define HID   512
#define PDIM  256
#define MROWS (BT * LSEQ)     // 65536 tokens
#define NCOLS 512             // 2*P (re | im)
#define KDIM  512
#define NCH   64              // scan chunks
#define TCH   128             // steps per chunk
#define NSEQ  (BT * 512)      // 4096 independent real 2-state scans

// GEMM tiling
#define BM 128
#define BN 128
#define BK 32                 // 64 B of bf16 per row -> SW64 swizzle
#define NK (KDIM / BK)        // 16 k-stages

// SMEM: 3 stages x 32KB. Per stage: Ah 8K | Al 8K | Bh 8K | Bl 8K
#define STG_BYTES 32768
#define SM_TOTAL  (3 * STG_BYTES)

// ---------------------------------------------------------------------------
// Static device scratch
// ---------------------------------------------------------------------------
__device__ __nv_bfloat16 g_W1h[KDIM * NCOLS];   // [n][k]
__device__ __nv_bfloat16 g_W1l[KDIM * NCOLS];
__device__ __nv_bfloat16 g_W2h[KDIM * NCOLS];
__device__ __nv_bfloat16 g_W2l[KDIM * NCOLS];
__device__ __nv_bfloat16 g_xh[(size_t)MROWS * NCOLS];
__device__ __nv_bfloat16 g_xl[(size_t)MROWS * NCOLS];
__device__ float g_Bu[(size_t)MROWS * NCOLS];           // 128 MB
__device__ __nv_bfloat16 g_ysh[(size_t)MROWS * NCOLS];  // 64 MB
__device__ __nv_bfloat16 g_ysl[(size_t)MROWS * NCOLS];  // 64 MB
__device__ float g_cf[PDIM * 8];
__device__ float g_mp[PDIM * 4];
__device__ float g_loc1[NCH * NSEQ];
__device__ float g_loc2[NCH * NSEQ];
__device__ float g_car1[NCH * NSEQ];
__device__ float g_car2[NCH * NSEQ];

// ---------------------------------------------------------------------------
// helpers
// ---------------------------------------------------------------------------
__device__ __forceinline__ uint32_t smem_u32(const void* p) {
    uint32_t a;
    asm("{ .reg .u64 t; cvta.to.shared.u64 t, %1; cvt.u32.u64 %0, t; }" : "=r"(a) : "l"(p));
    return a;
}
__device__ __forceinline__ void cp_async16(uint32_t dst, const void* src) {
    asm volatile("cp.async.cg.shared.global [%0], [%1], 16;" :: "r"(dst), "l"(src) : "memory");
}
__device__ __forceinline__ void cp_commit() {
    asm volatile("cp.async.commit_group;" ::: "memory");
}
template <int N>
__device__ __forceinline__ void cp_wait() {
    asm volatile("cp.async.wait_group %0;" :: "n"(N) : "memory");
}
__device__ __forceinline__ void ldsm_x4(uint32_t* r, uint32_t addr) {
    asm volatile("ldmatrix.sync.aligned.m8n8.x4.shared.b16 {%0,%1,%2,%3}, [%4];"
                 : "=r"(r[0]), "=r"(r[1]), "=r"(r[2]), "=r"(r[3]) : "r"(addr));
}
__device__ __forceinline__ void mma_bf16(float* c, const uint32_t* a, uint32_t b0, uint32_t b1) {
    asm volatile(
        "mma.sync.aligned.m16n8k16.row.col.f32.bf16.bf16.f32 "
        "{%0,%1,%2,%3}, {%4,%5,%6,%7}, {%8,%9}, {%0,%1,%2,%3};\n"
        : "+f"(c[0]), "+f"(c[1]), "+f"(c[2]), "+f"(c[3])
        : "r"(a[0]), "r"(a[1]), "r"(a[2]), "r"(a[3]), "r"(b0), "r"(b1));
}
__device__ __forceinline__ void split_f32(float v, __nv_bfloat16& hi, __nv_bfloat16& lo) {
    hi = __float2bfloat16(v);
    lo = __float2bfloat16(v - __bfloat162float(hi));
}
__device__ __forceinline__ uint32_t pack_bf16(__nv_bfloat16 a, __nv_bfloat16 b) {
    return (uint32_t)__bfloat16_as_ushort(a) | ((uint32_t)__bfloat16_as_ushort(b) << 16);
}

// ---------------------------------------------------------------------------
// Kernel 0: per-p coefficients + M^TCH
// ---------------------------------------------------------------------------
__global__ void prep_kernel(const float* __restrict__ steps_param,
                            const float* __restrict__ A_param) {
    int p = threadIdx.x;
    float s = 1.0f / (1.0f + expf(-steps_param[p]));
    float a = fmaxf(A_param[p], 0.0f);
    float c12 = -s * a;
    float c21 = s;
    float c22 = 1.0f - s * s * a;
    g_cf[p * 8 + 0] = s;
    g_cf[p * 8 + 1] = s * s;
    g_cf[p * 8 + 2] = c12;
    g_cf[p * 8 + 3] = c21;
    g_cf[p * 8 + 4] = c22;

    float ma = 1.0f, mb = c12, mc = c21, md = c22;
    #pragma unroll
    for (int i = 0; i < 7; i++) {
        float na = ma * ma + mb * mc;
        float nb = ma * mb + mb * md;
        float nc = mc * ma + md * mc;
        float nd = mc * mb + md * md;
        ma = na; mb = nb; mc = nc; md = nd;
    }
    g_mp[p * 4 + 0] = ma;
    g_mp[p * 4 + 1] = mb;
    g_mp[p * 4 + 2] = mc;
    g_mp[p * 4 + 3] = md;
}

// ---------------------------------------------------------------------------
// Kernel 1: pack weights into [n][k] bf16 hi/lo
// ---------------------------------------------------------------------------
__global__ void buildW_kernel(const float* __restrict__ Bp,
                              const float* __restrict__ Cp) {
    int idx = blockIdx.x * 256 + threadIdx.x;   // 0 .. 512*512-1
    {
        int k = idx >> 9;
        int n = idx & 511;
        float v = (n < 256) ? Bp[n * (HID * 2) + k * 2 + 0]
                            : Bp[(n - 256) * (HID * 2) + k * 2 + 1];
        __nv_bfloat16 hi, lo; split_f32(v, hi, lo);
        g_W1h[n * KDIM + k] = hi;
        g_W1l[n * KDIM + k] = lo;
    }
    {
        int k = idx >> 9;
        int n = idx & 511;
        float v = (k < 256) ? Cp[n * (PDIM * 2) + k * 2 + 0]
                            : -Cp[n * (PDIM * 2) + (k - 256) * 2 + 1];
        __nv_bfloat16 hi, lo; split_f32(v, hi, lo);
        g_W2h[n * KDIM + k] = hi;
        g_W2l[n * KDIM + k] = lo;
    }
}

// ---------------------------------------------------------------------------
// Kernel 2: split x into bf16 hi/lo
// ---------------------------------------------------------------------------
__global__ void __launch_bounds__(256) splitX_kernel(const float* __restrict__ x) {
    size_t i = ((size_t)blockIdx.x * 256 + threadIdx.x) << 2;
    float4 v = *(const float4*)(x + i);
    __nv_bfloat16 h0,l0,h1,l1,h2,l2,h3,l3;
    split_f32(v.x, h0, l0); split_f32(v.y, h1, l1);
    split_f32(v.z, h2, l2); split_f32(v.w, h3, l3);
    *(uint2*)(g_xh + i) = make_uint2(pack_bf16(h0, h1), pack_bf16(h2, h3));
    *(uint2*)(g_xl + i) = make_uint2(pack_bf16(l0, l1), pack_bf16(l2, l3));
}

// ---------------------------------------------------------------------------
// mma.sync GEMM, 3-stage cp.async ring, ldmatrix, SW64 swizzle.
// 128x128 block, K stages of 32, 256 thr = 8 warps (2m x 4n), warp 64x32.
// ---------------------------------------------------------------------------
template <int MODE>
__global__ void __launch_bounds__(256, 2)
mma_gemm(float* __restrict__ Cext, const float* __restrict__ xres,
         const float* __restrict__ Dv) {
    extern __shared__ __align__(128) char smem[];
    const uint32_t sb = smem_u32(smem);

    const __nv_bfloat16* Ah = (MODE == 0) ? g_xh : g_ysh;
    const __nv_bfloat16* Al = (MODE == 0) ? g_xl : g_ysl;
    const __nv_bfloat16* Wh = (MODE == 0) ? g_W1h : g_W2h;
    const __nv_bfloat16* Wl = (MODE == 0) ? g_W1l : g_W2l;
    float* Cout = (MODE == 0) ? g_Bu : Cext;

    const int tid  = threadIdx.x;
    const int lane = tid & 31;
    const int wid  = tid >> 5;
    const int warp_m = wid & 1;        // 0..1 -> 64 rows
    const int warp_n = wid >> 1;       // 0..3 -> 32 cols
    const int mBase = blockIdx.y << 7;
    const int nBase = blockIdx.x << 7;

    // ldmatrix lane mapping
    const int rl   = (lane & 7) + ((lane >> 3) & 1) * 8;
    const int kq16 = (lane >> 4) << 4;

    // A/B fragment base offsets (byte within matrix region) + swizzle xor
    uint32_t aOff[4], aXor[4];
    #pragma unroll
    for (int mt = 0; mt < 4; mt++) {
        int row = warp_m * 64 + mt * 16 + rl;
        aOff[mt] = row << 6;
        aXor[mt] = (row & 6) << 3;      // SW64: d ^ ((d>>3)&0x30)
    }
    uint32_t bOff[2], bXor[2];
    #pragma unroll
    for (int g = 0; g < 2; g++) {
        int row = warp_n * 32 + g * 16 + rl;
        bOff[g] = row << 6;
        bXor[g] = (row & 6) << 3;
    }

    float c[4][4][4];
    #pragma unroll
    for (int mt = 0; mt < 4; mt++)
        #pragma unroll
        for (int nt = 0; nt < 4; nt++)
            #pragma unroll
            for (int r = 0; r < 4; r++) c[mt][nt][r] = 0.0f;

    // ---- stage loader: 4 matrices x 128 rows x 4 segs(16B) = 2048 cp.async/CTA ----
    auto load_stage = [&](int kc, int buf) {
        const uint32_t s0 = sb + buf * STG_BYTES;
        const int k0 = kc * BK;
        #pragma unroll
        for (int it = 0; it < 8; it++) {
            int lin = tid + (it << 8);
            int mat = lin >> 9;            // compile-time per it
            int l2  = lin & 511;
            int r   = l2 >> 2;
            int s   = l2 & 3;
            uint32_t d = (r << 6) + (s << 4);
            d ^= (d >> 3) & 0x30;
            const __nv_bfloat16* src;
            int rowg;
            if (mat == 0)      { src = Ah; rowg = mBase + r; }
            else if (mat == 1) { src = Al; rowg = mBase + r; }
            else if (mat == 2) { src = Wh; rowg = nBase + r; }
            else               { src = Wl; rowg = nBase + r; }
            cp_async16(s0 + mat * 8192 + d, src + (size_t)rowg * KDIM + k0 + (s << 3));
        }
        cp_commit();
    };

    load_stage(0, 0);
    load_stage(1, 1);

    int buf = 0;
    for (int kc = 0; kc < NK; kc++) {
        cp_wait<1>();          // stage kc resident; kc+1 may be in flight
        __syncthreads();       // also protects buffer (kc+2)%3 computed at kc-1

        if (kc + 2 < NK) {
            int nb = buf + 2; if (nb >= 3) nb -= 3;
            load_stage(kc + 2, nb);
        } else {
            cp_commit();       // keep group accounting aligned for cp_wait<1>
        }

        const uint32_t s0 = sb + buf * STG_BYTES;
        const uint32_t aHi = s0, aLo = s0 + 8192, bHi = s0 + 16384, bLo = s0 + 24576;

        #pragma unroll
        for (int ks = 0; ks < 2; ks++) {
            const uint32_t kb = (ks << 5) + kq16;
            uint32_t ah[4][4], al[4][4];
            #pragma unroll
            for (int mt = 0; mt < 4; mt++) {
                ldsm_x4(ah[mt], aHi + aOff[mt] + (kb ^ aXor[mt]));
                ldsm_x4(al[mt], aLo + aOff[mt] + (kb ^ aXor[mt]));
            }
            #pragma unroll
            for (int g = 0; g < 2; g++) {
                uint32_t bh[4], bl[4];
                ldsm_x4(bh, bHi + bOff[g] + (kb ^ bXor[g]));
                ldsm_x4(bl, bLo + bOff[g] + (kb ^ bXor[g]));
                #pragma unroll
                for (int n2 = 0; n2 < 2; n2++) {
                    const int nt = g * 2 + n2;
                    const uint32_t b0h = bh[n2], b1h = bh[n2 + 2];
                    const uint32_t b0l = bl[n2], b1l = bl[n2 + 2];
                    #pragma unroll
                    for (int mt = 0; mt < 4; mt++) {
                        float* cc = c[mt][nt];
                        mma_bf16(cc, ah[mt], b0h, b1h);
                        mma_bf16(cc, ah[mt], b0l, b1l);
                        mma_bf16(cc, al[mt], b0h, b1h);
                    }
                }
            }
        }
        if (++buf == 3) buf = 0;
    }

    // ---- epilogue ----
    const int grp = lane >> 2;
    const int tig = lane & 3;
    #pragma unroll
    for (int nt = 0; nt < 4; nt++) {
        int col = nBase + warp_n * 32 + nt * 8 + (tig << 1);
        float2 d;
        if (MODE == 1) d = *(const float2*)(Dv + col);
        #pragma unroll
        for (int mt = 0; mt < 4; mt++) {
            int row0 = mBase + warp_m * 64 + mt * 16 + grp;
            size_t o0 = (size_t)row0 * NCOLS + col;
            size_t o1 = o0 + ((size_t)8 * NCOLS);
            float2 v0 = make_float2(c[mt][nt][0], c[mt][nt][1]);
            float2 v1 = make_float2(c[mt][nt][2], c[mt][nt][3]);
            if (MODE == 1) {
                float2 x0 = *(const float2*)(xres + o0);
                float2 x1 = *(const float2*)(xres + o1);
                v0.x += d.x * x0.x; v0.y += d.y * x0.y;
                v1.x += d.x * x1.x; v1.y += d.y * x1.y;
            }
            *(float2*)(Cout + o0) = v0;
            *(float2*)(Cout + o1) = v1;
        }
    }
}

// ---------------------------------------------------------------------------
// Scan pass 1: chunk-local scans with zero init; store final (z1,z2)
// ---------------------------------------------------------------------------
__global__ void __launch_bounds__(256) scan_pass1() {
    int c = blockIdx.x, b = blockIdx.y, z = blockIdx.z;
    int p = threadIdx.x;
    int n = (z << 8) + p;
    int sid = (b << 9) + n;

    float s1  = g_cf[p * 8 + 0];
    float s2  = g_cf[p * 8 + 1];
    float c12 = g_cf[p * 8 + 2];
    float c21 = g_cf[p * 8 + 3];
    float c22 = g_cf[p * 8 + 4];

    size_t base = ((size_t)(b * LSEQ + c * TCH) << 9) + n;
    float z1 = 0.0f, z2 = 0.0f;
    #pragma unroll 8
    for (int i = 0; i < TCH; i++) {
        float bu = g_Bu[base + ((size_t)i << 9)];
        float nz1 = fmaf(c12, z2, fmaf(s1, bu, z1));
        float nz2 = fmaf(c21, z1, fmaf(c22, z2, s2 * bu));
        z1 = nz1; z2 = nz2;
    }
    g_loc1[c * NSEQ + sid] = z1;
    g_loc2[c * NSEQ + sid] = z2;
}

// ---------------------------------------------------------------------------
// Scan pass 2: sequential carry scan across chunks (exclusive carries)
// ---------------------------------------------------------------------------
__global__ void __launch_bounds__(256) scan_pass2() {
    int sid = blockIdx.x * 256 + threadIdx.x;   // 0..4095
    int p = sid & 255;
    float m11 = g_mp[p * 4 + 0];
    float m12 = g_mp[p * 4 + 1];
    float m21 = g_mp[p * 4 + 2];
    float m22 = g_mp[p * 4 + 3];

    float c1 = 0.0f, c2 = 0.0f;
    for (int c = 0; c < NCH; c++) {
        g_car1[c * NSEQ + sid] = c1;
        g_car2[c * NSEQ + sid] = c2;
        float l1 = g_loc1[c * NSEQ + sid];
        float l2 = g_loc2[c * NSEQ + sid];
        float n1 = fmaf(m11, c1, fmaf(m12, c2, l1));
        float n2 = fmaf(m21, c1, fmaf(m22, c2, l2));
        c1 = n1; c2 = n2;
    }
}

// ---------------------------------------------------------------------------
// Scan pass 3: replay with carry-in, emit ys split to bf16 hi/lo
// ---------------------------------------------------------------------------
__global__ void __launch_bounds__(256) scan_pass3() {
    int c = blockIdx.x, b = blockIdx.y, z = blockIdx.z;
    int p = threadIdx.x;
    int n = (z << 8) + p;
    int sid = (b << 9) + n;

    float s1  = g_cf[p * 8 + 0];
    float s2  = g_cf[p * 8 + 1];
    float c12 = g_cf[p * 8 + 2];
    float c21 = g_cf[p * 8 + 3];
    float c22 = g_cf[p * 8 + 4];

    size_t base = ((size_t)(b * LSEQ + c * TCH) << 9) + n;
    float z1 = g_car1[c * NSEQ + sid];
    float z2 = g_car2[c * NSEQ + sid];
    #pragma unroll 8
    for (int i = 0; i < TCH; i++) {
        float bu = g_Bu[base + ((size_t)i << 9)];
        float nz1 = fmaf(c12, z2, fmaf(s1, bu, z1));
        float nz2 = fmaf(c21, z1, fmaf(c22, z2, s2 * bu));
        z1 = nz1; z2 = nz2;
        __nv_bfloat16 hi, lo; split_f32(z2, hi, lo);
        g_ysh[base + ((size_t)i << 9)] = hi;
        g_ysl[base + ((size_t)i << 9)] = lo;
    }
}

// ---------------------------------------------------------------------------
// Launch
// ---------------------------------------------------------------------------
extern "C" void kernel_launch(void* const* d_in, const int* in_sizes, int n_in,
                              void* d_out, int out_size) {
    const float* x  = (const float*)d_in[0];   // (8, 8192, 512)
    const float* sp = (const float*)d_in[1];   // (256,)
    const float* Ap = (const float*)d_in[2];   // (256,)
    const float* Bp = (const float*)d_in[3];   // (256, 512, 2)
    const float* Cp = (const float*)d_in[4];   // (512, 256, 2)
    const float* Dp = (const float*)d_in[5];   // (512,)
    float* y = (float*)d_out;                  // (8, 8192, 512)

    cudaFuncSetAttribute(mma_gemm<0>, cudaFuncAttributeMaxDynamicSharedMemorySize, SM_TOTAL);
    cudaFuncSetAttribute(mma_gemm<1>, cudaFuncAttributeMaxDynamicSharedMemorySize, SM_TOTAL);

    prep_kernel<<<1, 256>>>(sp, Ap);
    buildW_kernel<<<1024, 256>>>(Bp, Cp);
    splitX_kernel<<<(MROWS * NCOLS) / 1024, 256>>>(x);

    // GEMM1: Bu = x @ W1
    mma_gemm<0><<<dim3(NCOLS / BN, MROWS / BM), 256, SM_TOTAL>>>(nullptr, nullptr, nullptr);

    // Chunked linear scan (pass3 emits ys as bf16 hi/lo)
    scan_pass1<<<dim3(NCH, BT, 2), 256>>>();
    scan_pass2<<<16, 256>>>();
    scan_pass3<<<dim3(NCH, BT, 2), 256>>>();

    // GEMM2 + epilogue: y = ys @ W2 + D .* x
    mma_gemm<1><<<dim3(NCOLS / BN, MROWS / BM), 256, SM_TOTAL>>>(y, x, Dp);
}